// round 5
// baseline (speedup 1.0000x reference)
#include <cuda_runtime.h>

#define N_NODES 100000
#define N_EDGES 1250000
#define D 64
#define NPB 128  // nodes per block in the fused GEMM

typedef unsigned long long ull;

#define PACK_F32X2(out, lo, hi) \
    asm("mov.b64 %0, {%1, %2};" : "=l"(out) : "f"(lo), "f"(hi))
#define UNPACK_F32X2(lo, hi, in) \
    asm("mov.b64 {%0, %1}, %2;" : "=f"(lo), "=f"(hi) : "l"(in))
#define FMA_F32X2(d, a, b, c) \
    asm("fma.rn.f32x2 %0, %1, %2, %3;" : "=l"(d) : "l"(a), "l"(b), "l"(c))
#define TANH_APPROX(y, x) \
    asm("tanh.approx.f32 %0, %1;" : "=f"(y) : "f"(x))

// ---------------------------------------------------------------------------
// Kernel 1: edge scatter. 16 threads per edge, each handles one float4 chunk
// of the 64-float row: aggr[dst] += x[src], via red.global.add.v4.f32.
// Runtime-detects int64 vs int32 edge_index (JAX x64 ambiguity): node ids are
// < 2^31 so for little-endian int64 the odd 32-bit words are all zero.
// ---------------------------------------------------------------------------
__global__ void scatter_kernel(const float* __restrict__ x,
                               const int* __restrict__ e32,
                               float* __restrict__ aggr) {
    int t = blockIdx.x * blockDim.x + threadIdx.x;
    int e = t >> 4;
    if (e >= N_EDGES) return;
    int c = (t & 15) << 2;  // float offset within row (0,4,...,60)

    bool is64 = (e32[1] == 0) && (e32[3] == 0) && (e32[5] == 0) && (e32[7] == 0);

    int src, dst;
    if (is64) {
        src = e32[2 * e];
        dst = e32[2 * (N_EDGES + e)];
    } else {
        src = e32[e];
        dst = e32[N_EDGES + e];
    }

    float4 v = *reinterpret_cast<const float4*>(x + (long long)src * D + c);
    float* p = aggr + (long long)dst * D + c;
    asm volatile("red.global.add.v4.f32 [%0], {%1,%2,%3,%4};"
                 :: "l"(p), "f"(v.x), "f"(v.y), "f"(v.z), "f"(v.w)
                 : "memory");
}

// ---------------------------------------------------------------------------
// Kernel 2: fused  out = tanh( [aggr | x] @ [W_l ; W_r] + b )  per node,
// in place over the aggr scratch (= d_out). Packed fma.rn.f32x2 math.
//
// Block: 256 threads, NPB=128 nodes. Thread (tx, ng) computes cols
// [8tx, 8tx+8) of nodes ng*4 .. ng*4+3.  tx in [0,8), ng in [0,32).
// Shared: W (128x64, 32KB) + [aggr|x] rows (128x128, 64KB) + bias.
// ---------------------------------------------------------------------------
__global__ void __launch_bounds__(256, 2)
fused_gemm_kernel(const float* __restrict__ x,
                  const float* __restrict__ Wl,
                  const float* __restrict__ bl,
                  const float* __restrict__ Wr,
                  float* __restrict__ out) {
    extern __shared__ float sm[];
    float* sW  = sm;                 // [128][64]: rows 0..63 = W_l, 64..127 = W_r
    float* sAX = sm + 128 * 64;      // [NPB][128]: cols 0..63 = aggr, 64..127 = x
    float* sB  = sAX + NPB * 128;    // [64]

    int tid = threadIdx.x;
    int node0 = blockIdx.x * NPB;

    // --- stage weights ---
    float4* sW4 = reinterpret_cast<float4*>(sW);
    const float4* Wl4 = reinterpret_cast<const float4*>(Wl);
    const float4* Wr4 = reinterpret_cast<const float4*>(Wr);
#pragma unroll
    for (int i = 0; i < 4; i++) {
        int idx = tid + i * 256;
        sW4[idx]        = Wl4[idx];
        sW4[1024 + idx] = Wr4[idx];
    }
    if (tid < 64) sB[tid] = bl[tid];

    // --- stage [aggr | x] rows: NPB nodes * 32 float4 each ---
    float4* sAX4 = reinterpret_cast<float4*>(sAX);
#pragma unroll
    for (int i = tid; i < NPB * 32; i += 256) {
        int n = i >> 5;
        int c = i & 31;
        int node = node0 + n;
        float4 v = make_float4(0.f, 0.f, 0.f, 0.f);
        if (node < N_NODES) {
            if (c < 16) v = *reinterpret_cast<const float4*>(out + (long long)node * D + c * 4);
            else        v = *reinterpret_cast<const float4*>(x   + (long long)node * D + (c - 16) * 4);
        }
        sAX4[i] = v;
    }
    __syncthreads();

    int tx = tid & 7;    // 8 col-threads * 8 cols
    int ng = tid >> 3;   // 32 node-groups * 4 nodes

    // bias for cols 8tx..8tx+7, as 4 packed pairs
    ull bp[4];
    {
        float4 b0 = *reinterpret_cast<float4*>(sB + tx * 8);
        float4 b1 = *reinterpret_cast<float4*>(sB + tx * 8 + 4);
        PACK_F32X2(bp[0], b0.x, b0.y);
        PACK_F32X2(bp[1], b0.z, b0.w);
        PACK_F32X2(bp[2], b1.x, b1.y);
        PACK_F32X2(bp[3], b1.z, b1.w);
    }
    ull acc[4][4];  // [node][col-pair]
#pragma unroll
    for (int n = 0; n < 4; n++)
#pragma unroll
        for (int p = 0; p < 4; p++) acc[n][p] = bp[p];

    const float* r0 = sAX + (ng * 4 + 0) * 128;
    const float* r1 = sAX + (ng * 4 + 1) * 128;
    const float* r2 = sAX + (ng * 4 + 2) * 128;
    const float* r3 = sAX + (ng * 4 + 3) * 128;

    // W row k as packed pairs: 32 ull per row; thread uses pairs 4tx..4tx+3.
    const ulonglong2* sW2 = reinterpret_cast<const ulonglong2*>(sW);

#pragma unroll 4
    for (int k0 = 0; k0 < 128; k0 += 4) {
        float4 a0 = *reinterpret_cast<const float4*>(r0 + k0);
        float4 a1 = *reinterpret_cast<const float4*>(r1 + k0);
        float4 a2 = *reinterpret_cast<const float4*>(r2 + k0);
        float4 a3 = *reinterpret_cast<const float4*>(r3 + k0);
        const float* ap0 = reinterpret_cast<const float*>(&a0);
        const float* ap1 = reinterpret_cast<const float*>(&a1);
        const float* ap2 = reinterpret_cast<const float*>(&a2);
        const float* ap3 = reinterpret_cast<const float*>(&a3);
#pragma unroll
        for (int kk = 0; kk < 4; kk++) {
            int k = k0 + kk;
            ulonglong2 w01 = sW2[k * 16 + tx * 2];      // col pairs 2tx..
            ulonglong2 w23 = sW2[k * 16 + tx * 2 + 1];
            ull aa0, aa1, aa2, aa3;
            PACK_F32X2(aa0, ap0[kk], ap0[kk]);
            PACK_F32X2(aa1, ap1[kk], ap1[kk]);
            PACK_F32X2(aa2, ap2[kk], ap2[kk]);
            PACK_F32X2(aa3, ap3[kk], ap3[kk]);
            FMA_F32X2(acc[0][0], aa0, w01.x, acc[0][0]);
            FMA_F32X2(acc[0][1], aa0, w01.y, acc[0][1]);
            FMA_F32X2(acc[0][2], aa0, w23.x, acc[0][2]);
            FMA_F32X2(acc[0][3], aa0, w23.y, acc[0][3]);
            FMA_F32X2(acc[1][0], aa1, w01.x, acc[1][0]);
            FMA_F32X2(acc[1][1], aa1, w01.y, acc[1][1]);
            FMA_F32X2(acc[1][2], aa1, w23.x, acc[1][2]);
            FMA_F32X2(acc[1][3], aa1, w23.y, acc[1][3]);
            FMA_F32X2(acc[2][0], aa2, w01.x, acc[2][0]);
            FMA_F32X2(acc[2][1], aa2, w01.y, acc[2][1]);
            FMA_F32X2(acc[2][2], aa2, w23.x, acc[2][2]);
            FMA_F32X2(acc[2][3], aa2, w23.y, acc[2][3]);
            FMA_F32X2(acc[3][0], aa3, w01.x, acc[3][0]);
            FMA_F32X2(acc[3][1], aa3, w01.y, acc[3][1]);
            FMA_F32X2(acc[3][2], aa3, w23.x, acc[3][2]);
            FMA_F32X2(acc[3][3], aa3, w23.y, acc[3][3]);
        }
    }

    // --- tanh (HW MUFU) + store: 8 cols x 4 nodes ---
#pragma unroll
    for (int n = 0; n < 4; n++) {
        int node = node0 + ng * 4 + n;
        if (node < N_NODES) {
            float4 o0, o1;
            UNPACK_F32X2(o0.x, o0.y, acc[n][0]);
            UNPACK_F32X2(o0.z, o0.w, acc[n][1]);
            UNPACK_F32X2(o1.x, o1.y, acc[n][2]);
            UNPACK_F32X2(o1.z, o1.w, acc[n][3]);
            TANH_APPROX(o0.x, o0.x); TANH_APPROX(o0.y, o0.y);
            TANH_APPROX(o0.z, o0.z); TANH_APPROX(o0.w, o0.w);
            TANH_APPROX(o1.x, o1.x); TANH_APPROX(o1.y, o1.y);
            TANH_APPROX(o1.z, o1.z); TANH_APPROX(o1.w, o1.w);
            float* op = out + (long long)node * D + tx * 8;
            *reinterpret_cast<float4*>(op)     = o0;
            *reinterpret_cast<float4*>(op + 4) = o1;
        }
    }
}

// ---------------------------------------------------------------------------
extern "C" void kernel_launch(void* const* d_in, const int* in_sizes, int n_in,
                              void* d_out, int out_size) {
    const float* x  = (const float*)d_in[0];
    const int*   ei = (const int*)d_in[1];   // int32 or int64, probed on device
    const float* Wl = (const float*)d_in[2];
    const float* bl = (const float*)d_in[3];
    const float* Wr = (const float*)d_in[4];
    float* out = (float*)d_out;

    // 1) zero aggr scratch (= d_out) via memset node (HW path, capturable)
    cudaMemsetAsync(out, 0, (size_t)N_NODES * D * sizeof(float));

    // 2) edge scatter-add
    int threads = N_EDGES * 16;
    scatter_kernel<<<(threads + 255) / 256, 256>>>(x, ei, out);

    // 3) fused GEMM + bias + tanh (in place)
    const int smem = (128 * 64 + NPB * 128 + 64) * (int)sizeof(float);  // 98560 B
    static bool attr_set = false;
    if (!attr_set) {
        cudaFuncSetAttribute(fused_gemm_kernel,
                             cudaFuncAttributeMaxDynamicSharedMemorySize, smem);
        attr_set = true;
    }
    fused_gemm_kernel<<<(N_NODES + NPB - 1) / NPB, 256, smem>>>(x, Wl, bl, Wr, out);
}

// round 6
// speedup vs baseline: 1.0574x; 1.0574x over previous
#include <cuda_runtime.h>

#define N_NODES 100000
#define N_EDGES 1250000
#define D 64
#define NPB 64
#define SAX_STRIDE 68   // 64 + 4 pad floats: rows 4 apart -> 16 banks apart

typedef unsigned long long ull;

#define PACK_F32X2(out, lo, hi) \
    asm("mov.b64 %0, {%1, %2};" : "=l"(out) : "f"(lo), "f"(hi))
#define UNPACK_F32X2(lo, hi, in) \
    asm("mov.b64 {%0, %1}, %2;" : "=f"(lo), "=f"(hi) : "l"(in))
#define FMA_F32X2(d, a, b, c) \
    asm("fma.rn.f32x2 %0, %1, %2, %3;" : "=l"(d) : "l"(a), "l"(b), "l"(c))
#define TANH_APPROX(y, x) \
    asm("tanh.approx.f32 %0, %1;" : "=f"(y) : "f"(x))

// scratch for x @ W_r + b (static device memory: allowed)
__device__ float g_xwr[N_NODES * D];

// ---------------------------------------------------------------------------
// Scatter: 16 threads/edge, one red.global.add.v4.f32 each.
// Runtime int64/int32 probe (node ids < 2^31 -> int64 odd words all zero).
// ---------------------------------------------------------------------------
__global__ void scatter_kernel(const float* __restrict__ x,
                               const int* __restrict__ e32,
                               float* __restrict__ aggr) {
    int t = blockIdx.x * blockDim.x + threadIdx.x;
    int e = t >> 4;
    if (e >= N_EDGES) return;
    int c = (t & 15) << 2;

    bool is64 = (e32[1] == 0) && (e32[3] == 0) && (e32[5] == 0) && (e32[7] == 0);

    int src, dst;
    if (is64) {
        src = e32[2 * e];
        dst = e32[2 * (N_EDGES + e)];
    } else {
        src = e32[e];
        dst = e32[N_EDGES + e];
    }

    float4 v = *reinterpret_cast<const float4*>(x + (long long)src * D + c);
    float* p = aggr + (long long)dst * D + c;
    asm volatile("red.global.add.v4.f32 [%0], {%1,%2,%3,%4};"
                 :: "l"(p), "f"(v.x), "f"(v.y), "f"(v.z), "f"(v.w)
                 : "memory");
}

// ---------------------------------------------------------------------------
// Half-GEMM A: g_xwr = x @ W_r + b   (runs concurrent with scatter)
// 256 threads, NPB=64 nodes, thread (tx,ng) does cols [4tx,4tx+4) of
// nodes 4ng..4ng+3. Static smem: W 16KB + padded rows 17.4KB + bias.
// ---------------------------------------------------------------------------
__global__ void xwr_gemm_kernel(const float* __restrict__ x,
                                const float* __restrict__ Wr,
                                const float* __restrict__ bl) {
    __shared__ float sW[D * D];
    __shared__ float sAX[NPB * SAX_STRIDE];
    __shared__ float sB[D];

    int tid = threadIdx.x;
    int node0 = blockIdx.x * NPB;

    float4* sW4 = reinterpret_cast<float4*>(sW);
    const float4* W4 = reinterpret_cast<const float4*>(Wr);
#pragma unroll
    for (int i = 0; i < 4; i++) sW4[tid + i * 256] = W4[tid + i * 256];
    if (tid < 64) sB[tid] = bl[tid];

#pragma unroll
    for (int i = tid; i < NPB * 16; i += 256) {
        int n = i >> 4, c = i & 15;
        int node = node0 + n;
        float4 v = make_float4(0.f, 0.f, 0.f, 0.f);
        if (node < N_NODES)
            v = *reinterpret_cast<const float4*>(x + (long long)node * D + c * 4);
        *reinterpret_cast<float4*>(sAX + n * SAX_STRIDE + c * 4) = v;
    }
    __syncthreads();

    int tx = tid & 15;
    int ng = tid >> 4;

    float4 bb = reinterpret_cast<float4*>(sB)[tx];
    ull acc[4][2];
    {
        ull bxy, bzw;
        PACK_F32X2(bxy, bb.x, bb.y);
        PACK_F32X2(bzw, bb.z, bb.w);
#pragma unroll
        for (int n = 0; n < 4; n++) { acc[n][0] = bxy; acc[n][1] = bzw; }
    }

    const float* r0 = sAX + (ng * 4 + 0) * SAX_STRIDE;
    const float* r1 = sAX + (ng * 4 + 1) * SAX_STRIDE;
    const float* r2 = sAX + (ng * 4 + 2) * SAX_STRIDE;
    const float* r3 = sAX + (ng * 4 + 3) * SAX_STRIDE;
    const ulonglong2* sW2 = reinterpret_cast<const ulonglong2*>(sW);

#pragma unroll 4
    for (int k0 = 0; k0 < D; k0 += 4) {
        float4 a0 = *reinterpret_cast<const float4*>(r0 + k0);
        float4 a1 = *reinterpret_cast<const float4*>(r1 + k0);
        float4 a2 = *reinterpret_cast<const float4*>(r2 + k0);
        float4 a3 = *reinterpret_cast<const float4*>(r3 + k0);
        const float* ap0 = reinterpret_cast<const float*>(&a0);
        const float* ap1 = reinterpret_cast<const float*>(&a1);
        const float* ap2 = reinterpret_cast<const float*>(&a2);
        const float* ap3 = reinterpret_cast<const float*>(&a3);
#pragma unroll
        for (int kk = 0; kk < 4; kk++) {
            ulonglong2 w = sW2[(k0 + kk) * 16 + tx];
            ull aa0, aa1, aa2, aa3;
            PACK_F32X2(aa0, ap0[kk], ap0[kk]);
            PACK_F32X2(aa1, ap1[kk], ap1[kk]);
            PACK_F32X2(aa2, ap2[kk], ap2[kk]);
            PACK_F32X2(aa3, ap3[kk], ap3[kk]);
            FMA_F32X2(acc[0][0], aa0, w.x, acc[0][0]);
            FMA_F32X2(acc[0][1], aa0, w.y, acc[0][1]);
            FMA_F32X2(acc[1][0], aa1, w.x, acc[1][0]);
            FMA_F32X2(acc[1][1], aa1, w.y, acc[1][1]);
            FMA_F32X2(acc[2][0], aa2, w.x, acc[2][0]);
            FMA_F32X2(acc[2][1], aa2, w.y, acc[2][1]);
            FMA_F32X2(acc[3][0], aa3, w.x, acc[3][0]);
            FMA_F32X2(acc[3][1], aa3, w.y, acc[3][1]);
        }
    }

#pragma unroll
    for (int n = 0; n < 4; n++) {
        int node = node0 + ng * 4 + n;
        if (node < N_NODES) {
            float4 a;
            UNPACK_F32X2(a.x, a.y, acc[n][0]);
            UNPACK_F32X2(a.z, a.w, acc[n][1]);
            *reinterpret_cast<float4*>(g_xwr + (long long)node * D + tx * 4) = a;
        }
    }
}

// ---------------------------------------------------------------------------
// Half-GEMM B: out = tanh( aggr @ W_l + g_xwr ), in place over aggr (= d_out)
// ---------------------------------------------------------------------------
__global__ void final_gemm_kernel(const float* __restrict__ Wl,
                                  float* __restrict__ out) {
    __shared__ float sW[D * D];
    __shared__ float sAX[NPB * SAX_STRIDE];

    int tid = threadIdx.x;
    int node0 = blockIdx.x * NPB;

    float4* sW4 = reinterpret_cast<float4*>(sW);
    const float4* W4 = reinterpret_cast<const float4*>(Wl);
#pragma unroll
    for (int i = 0; i < 4; i++) sW4[tid + i * 256] = W4[tid + i * 256];

#pragma unroll
    for (int i = tid; i < NPB * 16; i += 256) {
        int n = i >> 4, c = i & 15;
        int node = node0 + n;
        float4 v = make_float4(0.f, 0.f, 0.f, 0.f);
        if (node < N_NODES)
            v = *reinterpret_cast<const float4*>(out + (long long)node * D + c * 4);
        *reinterpret_cast<float4*>(sAX + n * SAX_STRIDE + c * 4) = v;
    }
    __syncthreads();

    int tx = tid & 15;
    int ng = tid >> 4;

    ull acc[4][2];
#pragma unroll
    for (int n = 0; n < 4; n++) { acc[n][0] = 0ull; acc[n][1] = 0ull; }

    const float* r0 = sAX + (ng * 4 + 0) * SAX_STRIDE;
    const float* r1 = sAX + (ng * 4 + 1) * SAX_STRIDE;
    const float* r2 = sAX + (ng * 4 + 2) * SAX_STRIDE;
    const float* r3 = sAX + (ng * 4 + 3) * SAX_STRIDE;
    const ulonglong2* sW2 = reinterpret_cast<const ulonglong2*>(sW);

#pragma unroll 4
    for (int k0 = 0; k0 < D; k0 += 4) {
        float4 a0 = *reinterpret_cast<const float4*>(r0 + k0);
        float4 a1 = *reinterpret_cast<const float4*>(r1 + k0);
        float4 a2 = *reinterpret_cast<const float4*>(r2 + k0);
        float4 a3 = *reinterpret_cast<const float4*>(r3 + k0);
        const float* ap0 = reinterpret_cast<const float*>(&a0);
        const float* ap1 = reinterpret_cast<const float*>(&a1);
        const float* ap2 = reinterpret_cast<const float*>(&a2);
        const float* ap3 = reinterpret_cast<const float*>(&a3);
#pragma unroll
        for (int kk = 0; kk < 4; kk++) {
            ulonglong2 w = sW2[(k0 + kk) * 16 + tx];
            ull aa0, aa1, aa2, aa3;
            PACK_F32X2(aa0, ap0[kk], ap0[kk]);
            PACK_F32X2(aa1, ap1[kk], ap1[kk]);
            PACK_F32X2(aa2, ap2[kk], ap2[kk]);
            PACK_F32X2(aa3, ap3[kk], ap3[kk]);
            FMA_F32X2(acc[0][0], aa0, w.x, acc[0][0]);
            FMA_F32X2(acc[0][1], aa0, w.y, acc[0][1]);
            FMA_F32X2(acc[1][0], aa1, w.x, acc[1][0]);
            FMA_F32X2(acc[1][1], aa1, w.y, acc[1][1]);
            FMA_F32X2(acc[2][0], aa2, w.x, acc[2][0]);
            FMA_F32X2(acc[2][1], aa2, w.y, acc[2][1]);
            FMA_F32X2(acc[3][0], aa3, w.x, acc[3][0]);
            FMA_F32X2(acc[3][1], aa3, w.y, acc[3][1]);
        }
    }

#pragma unroll
    for (int n = 0; n < 4; n++) {
        int node = node0 + ng * 4 + n;
        if (node < N_NODES) {
            float4 xw = *reinterpret_cast<const float4*>(g_xwr + (long long)node * D + tx * 4);
            float4 a;
            UNPACK_F32X2(a.x, a.y, acc[n][0]);
            UNPACK_F32X2(a.z, a.w, acc[n][1]);
            a.x += xw.x; a.y += xw.y; a.z += xw.z; a.w += xw.w;
            TANH_APPROX(a.x, a.x);
            TANH_APPROX(a.y, a.y);
            TANH_APPROX(a.z, a.z);
            TANH_APPROX(a.w, a.w);
            *reinterpret_cast<float4*>(out + (long long)node * D + tx * 4) = a;
        }
    }
}

// ---------------------------------------------------------------------------
extern "C" void kernel_launch(void* const* d_in, const int* in_sizes, int n_in,
                              void* d_out, int out_size) {
    const float* x  = (const float*)d_in[0];
    const int*   ei = (const int*)d_in[1];
    const float* Wl = (const float*)d_in[2];
    const float* bl = (const float*)d_in[3];
    const float* Wr = (const float*)d_in[4];
    float* out = (float*)d_out;

    static cudaStream_t s2 = nullptr;
    static cudaEvent_t evFork = nullptr, evJoin = nullptr;
    if (s2 == nullptr) {
        cudaStreamCreateWithFlags(&s2, cudaStreamNonBlocking);
        cudaEventCreateWithFlags(&evFork, cudaEventDisableTiming);
        cudaEventCreateWithFlags(&evJoin, cudaEventDisableTiming);
    }

    const int gemm_blocks = (N_NODES + NPB - 1) / NPB;

    // fork: x @ W_r + b on side stream, concurrent with memset + scatter
    cudaEventRecord(evFork, 0);
    cudaStreamWaitEvent(s2, evFork, 0);
    xwr_gemm_kernel<<<gemm_blocks, 256, 0, s2>>>(x, Wr, bl);
    cudaEventRecord(evJoin, s2);

    // main: zero aggr (= d_out), scatter-add edges
    cudaMemsetAsync(out, 0, (size_t)N_NODES * D * sizeof(float));
    scatter_kernel<<<(N_EDGES * 16 + 255) / 256, 256>>>(x, ei, out);

    // join, then out = tanh(aggr @ W_l + g_xwr)
    cudaStreamWaitEvent((cudaStream_t)0, evJoin, 0);
    final_gemm_kernel<<<gemm_blocks, 256>>>(Wl, out);
}

// round 10
// speedup vs baseline: 1.4547x; 1.3758x over previous
#include <cuda_runtime.h>
#include <cuda_fp16.h>
#include <cstdint>

#define N_NODES 100000
#define N_EDGES 1250000
#define D 64
#define NPB 64  // nodes per block in the fused GEMM

typedef unsigned long long ull;

#define PACK_F32X2(out, lo, hi) \
    asm("mov.b64 %0, {%1, %2};" : "=l"(out) : "f"(lo), "f"(hi))
#define UNPACK_F32X2(lo, hi, in) \
    asm("mov.b64 {%0, %1}, %2;" : "=f"(lo), "=f"(hi) : "l"(in))
#define FMA_F32X2(d, a, b, c) \
    asm("fma.rn.f32x2 %0, %1, %2, %3;" : "=l"(d) : "l"(a), "l"(b), "l"(c))
#define TANH_APPROX(y, x) \
    asm("tanh.approx.f32 %0, %1;" : "=f"(y) : "f"(x))

// fp16 scratch (static device memory: allowed, no allocation)
__device__ __half g_aggr[N_NODES * D];   // 12.8 MB aggregation buffer
__device__ __half g_xh[N_NODES * D];     // 12.8 MB fp16 copy of x

// ---------------------------------------------------------------------------
// Prepass: x (f32) -> g_xh (fp16). 8 floats per thread.
// ---------------------------------------------------------------------------
__global__ void cvt_x_kernel(const float* __restrict__ x) {
    int i = blockIdx.x * blockDim.x + threadIdx.x;   // group of 8 floats
    if (i >= N_NODES * D / 8) return;
    const float4* xp = reinterpret_cast<const float4*>(x) + i * 2;
    float4 v0 = xp[0], v1 = xp[1];
    __half2 h[4];
    h[0] = __float22half2_rn(make_float2(v0.x, v0.y));
    h[1] = __float22half2_rn(make_float2(v0.z, v0.w));
    h[2] = __float22half2_rn(make_float2(v1.x, v1.y));
    h[3] = __float22half2_rn(make_float2(v1.z, v1.w));
    *(reinterpret_cast<uint4*>(g_xh) + i) = *reinterpret_cast<uint4*>(h);
}

// ---------------------------------------------------------------------------
// Scatter: 8 threads/edge; each loads 8 halves of x_h[src] (one LDG.128) and
// does one red.global.add.noftz.v4.f16x2 into g_aggr[dst] (one RED.128).
// Runtime probe of int64 vs int32 edge_index (ids < 2^31 -> odd words zero).
// ---------------------------------------------------------------------------
__global__ void scatter_kernel(const int* __restrict__ e32) {
    int t = blockIdx.x * blockDim.x + threadIdx.x;
    int e = t >> 3;
    if (e >= N_EDGES) return;
    int c = (t & 7) << 3;   // half offset within row (0,8,...,56)

    bool is64 = (e32[1] == 0) && (e32[3] == 0) && (e32[5] == 0) && (e32[7] == 0);

    int src, dst;
    if (is64) {
        src = e32[2 * e];
        dst = e32[2 * (N_EDGES + e)];
    } else {
        src = e32[e];
        dst = e32[N_EDGES + e];
    }

    uint4 v = *reinterpret_cast<const uint4*>(g_xh + (long long)src * D + c);
    __half* p = g_aggr + (long long)dst * D + c;
    asm volatile("red.global.add.noftz.v4.f16x2 [%0], {%1,%2,%3,%4};"
                 :: "l"(p), "r"(v.x), "r"(v.y), "r"(v.z), "r"(v.w)
                 : "memory");
}

// ---------------------------------------------------------------------------
// Fused GEMM: out = tanh( [aggr | x] @ [W_l ; W_r] + b ) per node.
// aggr read from g_aggr (fp16 -> f32); all math fp32 (packed fma.rn.f32x2).
// Block: 256 threads, NPB=64 nodes; thread (tx, ng) computes cols
// [4tx,4tx+4) of nodes 4ng..4ng+3.
// ---------------------------------------------------------------------------
__global__ void fused_gemm_kernel(const float* __restrict__ x,
                                  const float* __restrict__ Wl,
                                  const float* __restrict__ bl,
                                  const float* __restrict__ Wr,
                                  float* __restrict__ out) {
    extern __shared__ float sm[];
    float* sW  = sm;                 // [128][64]: rows 0..63 = W_l, 64..127 = W_r
    float* sAX = sm + 128 * 64;      // [NPB][128]: cols 0..63 = aggr, 64..127 = x
    float* sB  = sAX + NPB * 128;    // [64]

    int tid = threadIdx.x;
    int node0 = blockIdx.x * NPB;

    // --- stage weights ---
    float4* sW4 = reinterpret_cast<float4*>(sW);
    const float4* Wl4 = reinterpret_cast<const float4*>(Wl);
    const float4* Wr4 = reinterpret_cast<const float4*>(Wr);
#pragma unroll
    for (int i = 0; i < 4; i++) {
        int idx = tid + i * 256;
        sW4[idx]        = Wl4[idx];
        sW4[1024 + idx] = Wr4[idx];
    }
    if (tid < 64) sB[tid] = bl[tid];

    // --- stage aggr (fp16 -> f32): NPB nodes * 16 groups of 4 halves ---
    for (int i = tid; i < NPB * 16; i += 256) {
        int n = i >> 4, c = i & 15;
        int node = node0 + n;
        float4 v = make_float4(0.f, 0.f, 0.f, 0.f);
        if (node < N_NODES) {
            uint2 hw = *reinterpret_cast<const uint2*>(g_aggr + (long long)node * D + c * 4);
            __half2 h0 = *reinterpret_cast<__half2*>(&hw.x);
            __half2 h1 = *reinterpret_cast<__half2*>(&hw.y);
            float2 f0 = __half22float2(h0);
            float2 f1 = __half22float2(h1);
            v = make_float4(f0.x, f0.y, f1.x, f1.y);
        }
        *reinterpret_cast<float4*>(sAX + n * 128 + c * 4) = v;
    }
    // --- stage x rows (f32) ---
    for (int i = tid; i < NPB * 16; i += 256) {
        int n = i >> 4, c = i & 15;
        int node = node0 + n;
        float4 v = make_float4(0.f, 0.f, 0.f, 0.f);
        if (node < N_NODES)
            v = *reinterpret_cast<const float4*>(x + (long long)node * D + c * 4);
        *reinterpret_cast<float4*>(sAX + n * 128 + 64 + c * 4) = v;
    }
    __syncthreads();

    int tx = tid & 15;
    int ng = tid >> 4;

    float4 bb = reinterpret_cast<float4*>(sB)[tx];
    ull acc[4][2];
    {
        ull bxy, bzw;
        PACK_F32X2(bxy, bb.x, bb.y);
        PACK_F32X2(bzw, bb.z, bb.w);
#pragma unroll
        for (int n = 0; n < 4; n++) { acc[n][0] = bxy; acc[n][1] = bzw; }
    }

    const float* r0 = sAX + (ng * 4 + 0) * 128;
    const float* r1 = sAX + (ng * 4 + 1) * 128;
    const float* r2 = sAX + (ng * 4 + 2) * 128;
    const float* r3 = sAX + (ng * 4 + 3) * 128;
    const ulonglong2* sW2 = reinterpret_cast<const ulonglong2*>(sW);

#pragma unroll 4
    for (int k0 = 0; k0 < 128; k0 += 4) {
        float4 a0 = *reinterpret_cast<const float4*>(r0 + k0);
        float4 a1 = *reinterpret_cast<const float4*>(r1 + k0);
        float4 a2 = *reinterpret_cast<const float4*>(r2 + k0);
        float4 a3 = *reinterpret_cast<const float4*>(r3 + k0);
        const float* ap0 = reinterpret_cast<const float*>(&a0);
        const float* ap1 = reinterpret_cast<const float*>(&a1);
        const float* ap2 = reinterpret_cast<const float*>(&a2);
        const float* ap3 = reinterpret_cast<const float*>(&a3);
#pragma unroll
        for (int kk = 0; kk < 4; kk++) {
            ulonglong2 w = sW2[(k0 + kk) * 16 + tx];
            ull aa0, aa1, aa2, aa3;
            PACK_F32X2(aa0, ap0[kk], ap0[kk]);
            PACK_F32X2(aa1, ap1[kk], ap1[kk]);
            PACK_F32X2(aa2, ap2[kk], ap2[kk]);
            PACK_F32X2(aa3, ap3[kk], ap3[kk]);
            FMA_F32X2(acc[0][0], aa0, w.x, acc[0][0]);
            FMA_F32X2(acc[0][1], aa0, w.y, acc[0][1]);
            FMA_F32X2(acc[1][0], aa1, w.x, acc[1][0]);
            FMA_F32X2(acc[1][1], aa1, w.y, acc[1][1]);
            FMA_F32X2(acc[2][0], aa2, w.x, acc[2][0]);
            FMA_F32X2(acc[2][1], aa2, w.y, acc[2][1]);
            FMA_F32X2(acc[3][0], aa3, w.x, acc[3][0]);
            FMA_F32X2(acc[3][1], aa3, w.y, acc[3][1]);
        }
    }

#pragma unroll
    for (int n = 0; n < 4; n++) {
        int node = node0 + ng * 4 + n;
        if (node < N_NODES) {
            float4 a;
            UNPACK_F32X2(a.x, a.y, acc[n][0]);
            UNPACK_F32X2(a.z, a.w, acc[n][1]);
            TANH_APPROX(a.x, a.x);
            TANH_APPROX(a.y, a.y);
            TANH_APPROX(a.z, a.z);
            TANH_APPROX(a.w, a.w);
            *reinterpret_cast<float4*>(out + (long long)node * D + tx * 4) = a;
        }
    }
}

// ---------------------------------------------------------------------------
extern "C" void kernel_launch(void* const* d_in, const int* in_sizes, int n_in,
                              void* d_out, int out_size) {
    const float* x  = (const float*)d_in[0];
    const int*   ei = (const int*)d_in[1];
    const float* Wl = (const float*)d_in[2];
    const float* bl = (const float*)d_in[3];
    const float* Wr = (const float*)d_in[4];
    float* out = (float*)d_out;

    static void* aggr_ptr = nullptr;
    if (aggr_ptr == nullptr) cudaGetSymbolAddress(&aggr_ptr, g_aggr);

    // 1) zero fp16 aggr buffer (12.8 MB) + fp16 prepass of x (runs first)
    cudaMemsetAsync(aggr_ptr, 0, (size_t)N_NODES * D * sizeof(__half));
    cvt_x_kernel<<<(N_NODES * D / 8 + 255) / 256, 256>>>(x);

    // 2) fp16 edge scatter-add: 8 threads/edge
    scatter_kernel<<<(N_EDGES * 8 + 255) / 256, 256>>>(ei);

    // 3) fused GEMM + bias + tanh
    const int smem = (128 * 64 + NPB * 128 + 64) * (int)sizeof(float);  // 65792 B
    static bool attr_set = false;
    if (!attr_set) {
        cudaFuncSetAttribute(fused_gemm_kernel,
                             cudaFuncAttributeMaxDynamicSharedMemorySize, smem);
        attr_set = true;
    }
    fused_gemm_kernel<<<(N_NODES + NPB - 1) / NPB, 256, smem>>>(x, Wl, bl, Wr, out);
}